// round 12
// baseline (speedup 1.0000x reference)
#include <cuda_runtime.h>
#include <cstdint>

#define BB 4
#define CC 256
#define HH 64
#define WW 96
#define ND 21
#define HW (HH * WW)
#define CSTRIDE (4 * HW)     // advance 4 channels per chunk

// per-buffer geometry (float units); quad = 4 floats = 4 channels at one half-position
#define S2D 276              // V row pitch: 69 quads; 69 % 8 == 5 -> 8-lane phases conflict-free
#define SM1 2208             // A offset inside buffer (after 8 V rows)
#define S1R 192              // A row pitch: 48 quads
#define BUFSZ 2592           // floats per buffer
#define NBUF 8
#define SMEM_BYTES (NBUF * BUFSZ * 4)   // 82944 B (dynamic)

static __device__ __forceinline__ void fma2(unsigned long long& acc,
                                            unsigned long long a, unsigned long long b) {
    asm("fma.rn.f32x2 %0, %1, %2, %0;" : "+l"(acc) : "l"(a), "l"(b));
}
static __device__ __forceinline__ float pairsum(unsigned long long v) {
    float lo, hi;
    asm("mov.b64 {%0, %1}, %2;" : "=f"(lo), "=f"(hi) : "l"(v));
    return lo + hi;
}

// Grid: (dyg in [0,3), yp in [0,32), bz: b=bz>>1, parity p=bz&1). 768 blocks, 1 CTA/SM.
// Block 576 thr: l=tid&7 (V row), rest=tid>>3: g=rest%24 (2-half pixel group), dxg=rest/24.
// Thread: 2 pixels x=2(2g+kk)+p (kk<2), 7 dx=7dxg+j, rows y0 / y0+2 share V row l:
//   row y0   -> dyi = 7dyg+l   (valid l<=6);  row y0+2 -> dyi = 7dyg+l-1 (valid l>=1)
// V position pos = 2g+7dxg + (kk+j) = pos0 + t, t in [0,8). acc pair = (even-ch, odd-ch).
// Pipeline: 8 buffers, 1 barrier per 4 chunks, 2 prefetch registers.
__global__ __launch_bounds__(576, 1)
void corr_kernel(const float* __restrict__ in1, const float* __restrict__ in2,
                 float* __restrict__ out) {
    extern __shared__ __align__(16) float SM[];      // NBUF * BUFSZ floats

    const int dyg = blockIdx.x;
    const int yp  = blockIdx.y;
    const int b   = blockIdx.z >> 1;
    const int p   = blockIdx.z & 1;
    const int y0  = 4 * (yp >> 1) + (yp & 1);

    const int tid = threadIdx.x;
    for (int i = tid; i < NBUF * BUFSZ; i += 576) SM[i] = 0.f;   // halo/OOB stay zero

    // ---- staging: threads 0..479 load ONE channel-quad each (384 V + 96 A)
    const float* gp = in1;
    int so = -1;
    if (tid < 480) {
        if (tid < 384) {                        // V: row m, interior half u10
            int m   = tid / 48;
            int u10 = tid - 48 * m;
            int yy  = y0 + 14 * dyg + 2 * m - 20;
            bool v  = ((unsigned)yy < (unsigned)HH);
            gp = in2 + ((size_t)b * CC) * HW + (v ? yy : 0) * WW + (p + 2 * u10);
            so = v ? (m * S2D + 4 * (u10 + 10)) : -1;
        } else {                                // A: row yr (y0 or y0+2), half h
            int rem = tid - 384;
            int yr  = rem / 48;
            int h   = rem - 48 * yr;
            gp = in1 + ((size_t)b * CC) * HW + (y0 + 2 * yr) * WW + (2 * h + p);
            so = SM1 + yr * S1R + 4 * h;
        }
    }

    // ---- compute roles ----
    const int l    = tid & 7;
    const int rest = tid >> 3;
    const int g    = rest % 24;
    const int dxg  = rest / 24;
    const int pos0 = 2 * g + 7 * dxg;           // 0..60

    float4 pf0, pf1;
    auto ldg0 = [&]() {
        if (so >= 0) pf0 = make_float4(gp[0], gp[HW], gp[2 * HW], gp[3 * HW]);
        gp += CSTRIDE;
    };
    auto ldg1 = [&]() {
        if (so >= 0) pf1 = make_float4(gp[0], gp[HW], gp[2 * HW], gp[3 * HW]);
        gp += CSTRIDE;
    };
    auto sts0 = [&](int bsel) { if (so >= 0) *(float4*)(SM + bsel * BUFSZ + so) = pf0; };
    auto sts1 = [&](int bsel) { if (so >= 0) *(float4*)(SM + bsel * BUFSZ + so) = pf1; };

    unsigned long long aY[14], aZ[14];          // [j*2+kk]
#pragma unroll
    for (int i = 0; i < 14; i++) { aY[i] = 0ull; aZ[i] = 0ull; }

    auto compute = [&](int k) {
        const float* buf = SM + (k & 7) * BUFSZ;
        const ulonglong2* Vq = (const ulonglong2*)(buf + l * S2D) + pos0;
        const ulonglong2* Aq = (const ulonglong2*)(buf + SM1) + 2 * g;
        const ulonglong2 Ay0 = Aq[0], Ay1 = Aq[1];       // row y0,  kk=0/1
        const ulonglong2 Az0 = Aq[48], Az1 = Aq[49];     // row y0+2
#pragma unroll
        for (int t = 0; t < 8; t++) {
            ulonglong2 V = Vq[t];
            if (t <= 6) {                       // kk = 0, j = t
                const int idx = 2 * t;
                fma2(aY[idx], Ay0.x, V.x); fma2(aY[idx], Ay0.y, V.y);
                fma2(aZ[idx], Az0.x, V.x); fma2(aZ[idx], Az0.y, V.y);
            }
            if (t >= 1) {                       // kk = 1, j = t-1
                const int idx = 2 * (t - 1) + 1;
                fma2(aY[idx], Ay1.x, V.x); fma2(aY[idx], Ay1.y, V.y);
                fma2(aZ[idx], Az1.x, V.x); fma2(aZ[idx], Az1.y, V.y);
            }
        }
    };

    __syncthreads();                 // zeroing complete before first STS
    ldg0(); sts0(0);
    ldg1(); sts1(1);
    ldg0(); sts0(2);
    ldg1(); sts1(3);
    __syncthreads();

#pragma unroll 1
    for (int k = 0; k < 64; k += 4) {
        const bool pre = (k + 4 < 64);
        if (pre) { ldg0(); ldg1(); }            // chunks k+4, k+5 in flight
        compute(k);
        if (pre) sts0((k + 4) & 7);
        compute(k + 1);
        if (pre) sts1((k + 5) & 7);
        if (pre) { ldg0(); ldg1(); }            // chunks k+6, k+7 in flight
        compute(k + 2);
        if (pre) sts0((k + 6) & 7);
        compute(k + 3);
        if (pre) sts1((k + 7) & 7);
        __syncthreads();                        // one barrier per 4 chunks
    }

    // ---- epilogue ----
    const float scale = 1.f / 256.f;
    if (l <= 6) {                    // row y0, dyi = 7dyg+l
        const int dyi = 7 * dyg + l;
        for (int j = 0; j < 7; j++) {
            const int d = dyi * ND + 7 * dxg + j;
            float* op = out + (((size_t)b * ND * ND + d) * HH + y0) * WW + (4 * g + p);
            op[0] = pairsum(aY[2 * j]) * scale;
            op[2] = pairsum(aY[2 * j + 1]) * scale;
        }
    }
    if (l >= 1) {                    // row y0+2, dyi = 7dyg+l-1
        const int dyi = 7 * dyg + l - 1;
        for (int j = 0; j < 7; j++) {
            const int d = dyi * ND + 7 * dxg + j;
            float* op = out + (((size_t)b * ND * ND + d) * HH + (y0 + 2)) * WW + (4 * g + p);
            op[0] = pairsum(aZ[2 * j]) * scale;
            op[2] = pairsum(aZ[2 * j + 1]) * scale;
        }
    }
}

extern "C" void kernel_launch(void* const* d_in, const int* in_sizes, int n_in,
                              void* d_out, int out_size) {
    const float* in1 = (const float*)d_in[0];
    const float* in2 = (const float*)d_in[1];
    float* out = (float*)d_out;
    cudaFuncSetAttribute(corr_kernel, cudaFuncAttributeMaxDynamicSharedMemorySize, SMEM_BYTES);
    dim3 grid(3, 32, 8);
    corr_kernel<<<grid, 576, SMEM_BYTES>>>(in1, in2, out);
}

// round 13
// speedup vs baseline: 1.0785x; 1.0785x over previous
#include <cuda_runtime.h>
#include <cstdint>

#define BB 4
#define CC 256
#define HH 64
#define WW 96
#define ND 21
#define HW (HH * WW)
#define CSTRIDE (4 * HW)     // advance 4 channels per chunk (floats)

// per-buffer geometry (float units); quad = 4 floats = 4 channels at one half-position
#define S2D 276              // V row pitch: 69 quads; 69 % 8 == 5 -> 8-lane phases conflict-free
#define SM1 2208             // A offset inside buffer (after 8 V rows)
#define S1R 192              // A row pitch: 48 quads
#define BUFSZ 2592           // floats per buffer
#define NBUF 8
#define SMEM_BYTES (NBUF * BUFSZ * 4)   // 82944 B (dynamic, 1 CTA/SM)

static __device__ __forceinline__ void fma2(unsigned long long& acc,
                                            unsigned long long a, unsigned long long b) {
    asm("fma.rn.f32x2 %0, %1, %2, %0;" : "+l"(acc) : "l"(a), "l"(b));
}
static __device__ __forceinline__ float pairsum(unsigned long long v) {
    float lo, hi;
    asm("mov.b64 {%0, %1}, %2;" : "=f"(lo), "=f"(hi) : "l"(v));
    return lo + hi;
}
static __device__ __forceinline__ void cp4(uint32_t sa, const float* g) {
    asm volatile("cp.async.ca.shared.global [%0], [%1], 4;" :: "r"(sa), "l"(g));
}
static __device__ __forceinline__ void cp_commit() {
    asm volatile("cp.async.commit_group;" ::: "memory");
}
template <int N>
static __device__ __forceinline__ void cp_wait() {
    asm volatile("cp.async.wait_group %0;" :: "n"(N) : "memory");
}
static __device__ __forceinline__ uint32_t s2u(const void* p) {
    uint32_t a;
    asm("{ .reg .u64 t; cvta.to.shared.u64 t, %1; cvt.u32.u64 %0, t; }" : "=r"(a) : "l"(p));
    return a;
}

// Grid: (dyg in [0,3), yp in [0,32), bz: b=bz>>1, parity p=bz&1). 768 blocks, 1 CTA/SM.
// Block 384 thr: l=tid&7 (V row), rest=tid>>3: g=rest%16 (3-half pixel group), dxg=rest/16.
// Thread: 3 pixels x=2(3g+kk)+p (kk<3), 7 dx=7dxg+j, rows y0 / y0+2 share V row l:
//   row y0   -> dyi = 7dyg+l   (valid l<=6);  row y0+2 -> dyi = 7dyg+l-1 (valid l>=1)
// V position pos = 3g+7dxg + (kk+j) = pos0 + t, t in [0,9). acc pair = (even-ch, odd-ch).
// Staging: cp.async (4B x 4 channels per quad), 1 commit group per chunk, 6-deep.
__global__ __launch_bounds__(384, 1)
void corr_kernel(const float* __restrict__ in1, const float* __restrict__ in2,
                 float* __restrict__ out) {
    extern __shared__ __align__(16) float SM[];      // NBUF * BUFSZ floats

    const int dyg = blockIdx.x;
    const int yp  = blockIdx.y;
    const int b   = blockIdx.z >> 1;
    const int p   = blockIdx.z & 1;
    const int y0  = 4 * (yp >> 1) + (yp & 1);
    const uint32_t smu = s2u(SM);

    const int tid = threadIdx.x;
    for (int i = tid; i < NBUF * BUFSZ; i += 384) SM[i] = 0.f;   // halo/OOB stay zero

    // ---- staging roles: every thread stages V quad tid; tid<96 also stages A quad
    const float* gp0;
    int so0 = -1;                     // byte offset within buffer, or -1 (OOB row)
    {
        int m   = tid / 48;           // V row
        int u10 = tid - 48 * m;       // interior half-position
        int yy  = y0 + 14 * dyg + 2 * m - 20;
        bool v  = ((unsigned)yy < (unsigned)HH);
        gp0 = in2 + ((size_t)b * CC) * HW + (v ? yy : 0) * WW + (p + 2 * u10);
        so0 = v ? 4 * (m * S2D + 4 * (u10 + 10)) : -1;
    }
    const float* gp1 = in1;
    int so1 = -1;
    if (tid < 96) {
        int yr = tid / 48;            // A row (y0 or y0+2)
        int h  = tid - 48 * yr;
        gp1 = in1 + ((size_t)b * CC) * HW + (y0 + 2 * yr) * WW + (2 * h + p);
        so1 = 4 * (SM1 + yr * S1R + 4 * h);
    }

    auto stage = [&](int bsel) {      // one commit group per chunk
        uint32_t base = smu + (uint32_t)(bsel * (BUFSZ * 4));
        if (so0 >= 0) {
#pragma unroll
            for (int c = 0; c < 4; c++) cp4(base + so0 + 4 * c, gp0 + c * HW);
        }
        gp0 += CSTRIDE;
        if (so1 >= 0) {
#pragma unroll
            for (int c = 0; c < 4; c++) cp4(base + so1 + 4 * c, gp1 + c * HW);
            gp1 += CSTRIDE;
        }
        cp_commit();
    };

    // ---- compute roles ----
    const int l    = tid & 7;
    const int rest = tid >> 3;
    const int g    = rest & 15;
    const int dxg  = rest >> 4;
    const int pos0 = 3 * g + 7 * dxg;           // 0..59

    unsigned long long aY[21], aZ[21];          // [j*3+kk]
#pragma unroll
    for (int i = 0; i < 21; i++) { aY[i] = 0ull; aZ[i] = 0ull; }

    auto compute = [&](int k) {
        const float* buf = SM + (k & 7) * BUFSZ;
        const ulonglong2* Vq = (const ulonglong2*)(buf + l * S2D) + pos0;
        const ulonglong2* Aq = (const ulonglong2*)(buf + SM1) + 3 * g;
        ulonglong2 Ay[3], Az[3];
#pragma unroll
        for (int kk = 0; kk < 3; kk++) { Ay[kk] = Aq[kk]; Az[kk] = Aq[48 + kk]; }
#pragma unroll
        for (int t = 0; t < 9; t++) {
            ulonglong2 V = Vq[t];
            const int klo = (t > 6) ? (t - 6) : 0;
            const int khi = (t < 2) ? t : 2;
#pragma unroll
            for (int kk = klo; kk <= khi; kk++) {
                const int idx = (t - kk) * 3 + kk;   // j*3+kk
                fma2(aY[idx], Ay[kk].x, V.x); fma2(aY[idx], Ay[kk].y, V.y);
                fma2(aZ[idx], Az[kk].x, V.x); fma2(aZ[idx], Az[kk].y, V.y);
            }
        }
    };

    __syncthreads();                  // zero-stores complete before any cp.async lands
    stage(0); stage(1); stage(2); stage(3);

#pragma unroll 1
    for (int k = 0; k < 64; k += 2) {
        if (k + 4 < 64) {
            stage((k + 4) & 7);
            stage((k + 5) & 7);
            cp_wait<2>();             // chunks k, k+1 (and older) complete in this thread
        } else {
            cp_wait<0>();             // tail: drain everything
        }
        __syncthreads();              // cross-thread visibility of staged data
        compute(k);
        compute(k + 1);
    }

    // ---- epilogue ----
    const float scale = 1.f / 256.f;
    if (l <= 6) {                     // row y0, dyi = 7dyg+l
        const int dyi = 7 * dyg + l;
        for (int j = 0; j < 7; j++) {
            const int d = dyi * ND + 7 * dxg + j;
            float* op = out + (((size_t)b * ND * ND + d) * HH + y0) * WW + (6 * g + p);
#pragma unroll
            for (int kk = 0; kk < 3; kk++)
                op[2 * kk] = pairsum(aY[j * 3 + kk]) * scale;
        }
    }
    if (l >= 1) {                     // row y0+2, dyi = 7dyg+l-1
        const int dyi = 7 * dyg + l - 1;
        for (int j = 0; j < 7; j++) {
            const int d = dyi * ND + 7 * dxg + j;
            float* op = out + (((size_t)b * ND * ND + d) * HH + (y0 + 2)) * WW + (6 * g + p);
#pragma unroll
            for (int kk = 0; kk < 3; kk++)
                op[2 * kk] = pairsum(aZ[j * 3 + kk]) * scale;
        }
    }
}

extern "C" void kernel_launch(void* const* d_in, const int* in_sizes, int n_in,
                              void* d_out, int out_size) {
    const float* in1 = (const float*)d_in[0];
    const float* in2 = (const float*)d_in[1];
    float* out = (float*)d_out;
    cudaFuncSetAttribute(corr_kernel, cudaFuncAttributeMaxDynamicSharedMemorySize, SMEM_BYTES);
    dim3 grid(3, 32, 8);
    corr_kernel<<<grid, 384, SMEM_BYTES>>>(in1, in2, out);
}

// round 14
// speedup vs baseline: 1.1197x; 1.0382x over previous
#include <cuda_runtime.h>
#include <cstdint>

#define BB 4
#define CC 256
#define HH 64
#define WW 96
#define ND 21
#define HW (HH * WW)

// chunk = 8 channels; 32 chunks total
#define NCH 32
#define GSTRIDE (8 * HW)        // global float stride per chunk

// per-buffer geometry (float units); position entry = 8 floats (8 channels)
#define VROW 556                // V row pitch: 139 quads, 139 % 8 == 3 -> conflict-free
#define AOFF 4448               // A region after 8 V rows
#define AROW 384                // A row pitch (48 positions x 8 ch)
#define BUFSZ 5216              // floats per buffer
#define NBUF 8
#define BUFBYTES (BUFSZ * 4)
#define SMEM_BYTES (NBUF * BUFBYTES)    // 166912 B (dynamic, 1 CTA/SM)

static __device__ __forceinline__ void fma2(unsigned long long& acc,
                                            unsigned long long a, unsigned long long b) {
    asm("fma.rn.f32x2 %0, %1, %2, %0;" : "+l"(acc) : "l"(a), "l"(b));
}
static __device__ __forceinline__ float pairsum(unsigned long long v) {
    float lo, hi;
    asm("mov.b64 {%0, %1}, %2;" : "=f"(lo), "=f"(hi) : "l"(v));
    return lo + hi;
}
static __device__ __forceinline__ void cp4(uint32_t sa, const float* g) {
    asm volatile("cp.async.ca.shared.global [%0], [%1], 4;" :: "r"(sa), "l"(g));
}
static __device__ __forceinline__ void cp_commit() {
    asm volatile("cp.async.commit_group;" ::: "memory");
}
template <int N>
static __device__ __forceinline__ void cp_wait() {
    asm volatile("cp.async.wait_group %0;" :: "n"(N) : "memory");
}
static __device__ __forceinline__ uint32_t s2u(const void* p) {
    uint32_t a;
    asm("{ .reg .u64 t; cvta.to.shared.u64 t, %1; cvt.u32.u64 %0, t; }" : "=r"(a) : "l"(p));
    return a;
}

// Grid: (dyg in [0,3), yp in [0,32), bz: b=bz>>1, parity p=bz&1). 768 blocks, 1 CTA/SM.
// Block 384 thr: l=tid&7 (V row), rest=tid>>3: g=rest%16 (3-half pixel group), dxg=rest/16.
// Thread: 3 pixels x=2(3g+kk)+p (kk<3), 7 dx=7dxg+j, rows y0 / y0+2 share V row l.
// Chunk = 8 channels processed as two channel-quads q=0,1 -> acc pair (even, odd ch).
__global__ __launch_bounds__(384, 1)
void corr_kernel(const float* __restrict__ in1, const float* __restrict__ in2,
                 float* __restrict__ out) {
    extern __shared__ __align__(16) float SM[];

    const int dyg = blockIdx.x;
    const int yp  = blockIdx.y;
    const int b   = blockIdx.z >> 1;
    const int p   = blockIdx.z & 1;
    const int y0  = 4 * (yp >> 1) + (yp & 1);
    const uint32_t smu = s2u(SM);

    const int tid = threadIdx.x;
    for (int i = tid; i < NBUF * BUFSZ; i += 384) SM[i] = 0.f;   // halo/OOB stay zero

    // ---- staging roles: thread stages one V position (8 ch); tid<96 also one A position
    const float* gp0;
    int so0 = -1;                 // byte offset within buffer, or -1 (OOB row)
    {
        int m  = tid / 48;        // V row
        int u  = tid - 48 * m;    // interior half-position
        int yy = y0 + 14 * dyg + 2 * m - 20;
        bool v = ((unsigned)yy < (unsigned)HH);
        gp0 = in2 + ((size_t)b * CC) * HW + (v ? yy : 0) * WW + (p + 2 * u);
        so0 = v ? 4 * (m * VROW + (u + 10) * 8) : -1;
    }
    const float* gp1 = in1;
    int so1 = -1;
    if (tid < 96) {
        int yr = tid / 48;        // A row (y0 or y0+2)
        int h  = tid - 48 * yr;
        gp1 = in1 + ((size_t)b * CC) * HW + (y0 + 2 * yr) * WW + (2 * h + p);
        so1 = 4 * (AOFF + yr * AROW + h * 8);
    }

    auto stage = [&](int bsel) {  // one commit group per 8-channel chunk
        uint32_t base = smu + (uint32_t)(bsel * BUFBYTES);
        if (so0 >= 0) {
#pragma unroll
            for (int c = 0; c < 8; c++) cp4(base + so0 + 4 * c, gp0 + c * HW);
        }
        gp0 += GSTRIDE;
        if (so1 >= 0) {
#pragma unroll
            for (int c = 0; c < 8; c++) cp4(base + so1 + 4 * c, gp1 + c * HW);
            gp1 += GSTRIDE;
        }
        cp_commit();
    };

    // ---- compute roles ----
    const int l    = tid & 7;
    const int rest = tid >> 3;
    const int g    = rest & 15;
    const int dxg  = rest >> 4;
    const int pos0 = 3 * g + 7 * dxg;            // 0..59

    unsigned long long aY[21], aZ[21];           // [j*3+kk]
#pragma unroll
    for (int i = 0; i < 21; i++) { aY[i] = 0ull; aZ[i] = 0ull; }

    auto compute = [&](int k) {
        const float* buf = SM + (k & 7) * BUFSZ;
#pragma unroll 1
        for (int q = 0; q < 2; q++) {            // two independent channel-quads
            const float* Vb = buf + l * VROW + pos0 * 8 + q * 4;
            const float* Ab = buf + AOFF + 3 * g * 8 + q * 4;
            ulonglong2 Ay[3], Az[3];
#pragma unroll
            for (int kk = 0; kk < 3; kk++) {
                Ay[kk] = *(const ulonglong2*)(Ab + kk * 8);
                Az[kk] = *(const ulonglong2*)(Ab + AROW + kk * 8);
            }
#pragma unroll
            for (int t = 0; t < 9; t++) {
                ulonglong2 V = *(const ulonglong2*)(Vb + t * 8);
                const int klo = (t > 6) ? (t - 6) : 0;
                const int khi = (t < 2) ? t : 2;
#pragma unroll
                for (int kk = klo; kk <= khi; kk++) {
                    const int idx = (t - kk) * 3 + kk;   // j*3+kk
                    fma2(aY[idx], Ay[kk].x, V.x); fma2(aY[idx], Ay[kk].y, V.y);
                    fma2(aZ[idx], Az[kk].x, V.x); fma2(aZ[idx], Az[kk].y, V.y);
                }
            }
        }
    };

    __syncthreads();              // zero-stores complete before any cp.async lands
    stage(0); stage(1); stage(2); stage(3);

#pragma unroll 1
    for (int k = 0; k < NCH; k += 2) {
        if (k + 4 < NCH) {
            stage((k + 4) & 7);
            stage((k + 5) & 7);
            cp_wait<2>();         // chunks <= k+3 complete in this thread
        } else {
            cp_wait<0>();         // tail: drain everything
        }
        __syncthreads();          // cross-thread visibility of staged data
        compute(k);
        compute(k + 1);
    }

    // ---- epilogue ----
    const float scale = 1.f / 256.f;
    if (l <= 6) {                 // row y0, dyi = 7dyg+l
        const int dyi = 7 * dyg + l;
        for (int j = 0; j < 7; j++) {
            const int d = dyi * ND + 7 * dxg + j;
            float* op = out + (((size_t)b * ND * ND + d) * HH + y0) * WW + (6 * g + p);
#pragma unroll
            for (int kk = 0; kk < 3; kk++)
                op[2 * kk] = pairsum(aY[j * 3 + kk]) * scale;
        }
    }
    if (l >= 1) {                 // row y0+2, dyi = 7dyg+l-1
        const int dyi = 7 * dyg + l - 1;
        for (int j = 0; j < 7; j++) {
            const int d = dyi * ND + 7 * dxg + j;
            float* op = out + (((size_t)b * ND * ND + d) * HH + (y0 + 2)) * WW + (6 * g + p);
#pragma unroll
            for (int kk = 0; kk < 3; kk++)
                op[2 * kk] = pairsum(aZ[j * 3 + kk]) * scale;
        }
    }
}

extern "C" void kernel_launch(void* const* d_in, const int* in_sizes, int n_in,
                              void* d_out, int out_size) {
    const float* in1 = (const float*)d_in[0];
    const float* in2 = (const float*)d_in[1];
    float* out = (float*)d_out;
    cudaFuncSetAttribute(corr_kernel, cudaFuncAttributeMaxDynamicSharedMemorySize, SMEM_BYTES);
    dim3 grid(3, 32, 8);
    corr_kernel<<<grid, 384, SMEM_BYTES>>>(in1, in2, out);
}